// round 7
// baseline (speedup 1.0000x reference)
#include <cuda_runtime.h>
#include <math.h>
#include <stdint.h>

#define BATCH 2
#define SEQN 2048
#define SEQM 2048
#define DIM 1024
#define HEADS 16
#define DH 64
#define ATT_SCALE 0.125f
#define LN_EPS 1e-5f

// ---------------- scratch (static device memory; no allocation) ----------------
__device__ float g_xn[BATCH * SEQN * DIM];
__device__ float g_cn[BATCH * SEQM * DIM];
__device__ float g_q [BATCH * SEQN * DIM];
__device__ float g_k [BATCH * SEQM * DIM];
__device__ float g_v [BATCH * SEQM * DIM];
__device__ float g_ao[BATCH * SEQN * DIM];

// ---------------- helpers ----------------
__device__ __forceinline__ uint32_t f2tf(float f) {
    uint32_t r;
    asm("cvt.rna.tf32.f32 %0, %1;" : "=r"(r) : "f"(f));
    return r;
}

__device__ __forceinline__ void mma_tf32(float* c, const uint32_t* a, uint32_t b0, uint32_t b1) {
    asm volatile(
        "mma.sync.aligned.m16n8k8.row.col.f32.tf32.tf32.f32 "
        "{%0,%1,%2,%3}, {%4,%5,%6,%7}, {%8,%9}, {%0,%1,%2,%3};\n"
        : "+f"(c[0]), "+f"(c[1]), "+f"(c[2]), "+f"(c[3])
        : "r"(a[0]), "r"(a[1]), "r"(a[2]), "r"(a[3]), "r"(b0), "r"(b1));
}

// ---------------- LayerNorm: one block per row ----------------
__global__ __launch_bounds__(256) void ln_kernel(
    const float* __restrict__ x, const float* __restrict__ ctx,
    const float* __restrict__ w, const float* __restrict__ b,
    float* __restrict__ xn, float* __restrict__ cn)
{
    int row = blockIdx.x;
    const float* in;
    float* out;
    if (row < BATCH * SEQN) {
        in = x + (size_t)row * DIM;
        out = xn + (size_t)row * DIM;
    } else {
        int r = row - BATCH * SEQN;
        in = ctx + (size_t)r * DIM;
        out = cn + (size_t)r * DIM;
    }
    int tid = threadIdx.x;
    float4 v4 = ((const float4*)in)[tid];
    float s  = v4.x + v4.y + v4.z + v4.w;
    float s2 = v4.x*v4.x + v4.y*v4.y + v4.z*v4.z + v4.w*v4.w;

    #pragma unroll
    for (int off = 16; off > 0; off >>= 1) {
        s  += __shfl_xor_sync(0xffffffffu, s,  off);
        s2 += __shfl_xor_sync(0xffffffffu, s2, off);
    }
    __shared__ float rs[8], rs2[8];
    int wid = tid >> 5, lid = tid & 31;
    if (lid == 0) { rs[wid] = s; rs2[wid] = s2; }
    __syncthreads();
    if (wid == 0) {
        s  = (lid < 8) ? rs[lid]  : 0.f;
        s2 = (lid < 8) ? rs2[lid] : 0.f;
        #pragma unroll
        for (int off = 4; off > 0; off >>= 1) {
            s  += __shfl_xor_sync(0xffffffffu, s,  off);
            s2 += __shfl_xor_sync(0xffffffffu, s2, off);
        }
        if (lid == 0) { rs[0] = s; rs2[0] = s2; }
    }
    __syncthreads();
    float mu  = rs[0] * (1.0f / DIM);
    float var = rs2[0] * (1.0f / DIM) - mu * mu;
    float inv = rsqrtf(var + LN_EPS);

    float4 w4 = ((const float4*)w)[tid];
    float4 b4 = ((const float4*)b)[tid];
    float4 o4;
    o4.x = (v4.x - mu) * inv * w4.x + b4.x;
    o4.y = (v4.y - mu) * inv * w4.y + b4.y;
    o4.z = (v4.z - mu) * inv * w4.z + b4.z;
    o4.w = (v4.w - mu) * inv * w4.w + b4.w;
    ((float4*)out)[tid] = o4;
}

// ---------------- tf32 GEMM (pipelined): C[M,N] = A[M,K] @ W[N,K]^T (+bias) ----
// 128x128 tile, BK=32, 256 threads (8 warps, 2x4), warp tile 64x32.
// Double-buffered smem, one __syncthreads per K-chunk.
#define SAS 36   // smem row stride (32 + 4 pad) -> conflict-free fragment loads
#define GSTG (128 * SAS)

__global__ __launch_bounds__(256) void gemm_tf32(
    const float* __restrict__ A, const float* __restrict__ W,
    float* __restrict__ C, const float* __restrict__ bias)
{
    extern __shared__ uint32_t gsm[];
    uint32_t* sA = gsm;              // 2 stages of [128][SAS]
    uint32_t* sB = gsm + 2 * GSTG;   // 2 stages of [128][SAS]

    int tid = threadIdx.x;
    int lane = tid & 31, w = tid >> 5;
    int g = lane >> 2, q = lane & 3;
    int wm = (w >> 2) * 64, wn = (w & 3) * 32;
    int m0 = blockIdx.y * 128, n0 = blockIdx.x * 128;

    int lr = tid >> 1;          // 0..127
    int lk = (tid & 1) * 16;    // 0 or 16

    const float* Ap = A + (size_t)(m0 + lr) * DIM + lk;
    const float* Wp = W + (size_t)(n0 + lr) * DIM + lk;

    float acc[4][4][4];
    #pragma unroll
    for (int mt = 0; mt < 4; mt++)
        #pragma unroll
        for (int nt = 0; nt < 4; nt++)
            #pragma unroll
            for (int i = 0; i < 4; i++) acc[mt][nt][i] = 0.f;

    float4 av[4], wv[4];
    // preload chunk 0 into stage 0
    #pragma unroll
    for (int i = 0; i < 4; i++) {
        av[i] = *(const float4*)(Ap + i * 4);
        wv[i] = *(const float4*)(Wp + i * 4);
    }
    #pragma unroll
    for (int i = 0; i < 4; i++) {
        uint32_t* d = &sA[lr * SAS + lk + i * 4];
        d[0] = f2tf(av[i].x); d[1] = f2tf(av[i].y);
        d[2] = f2tf(av[i].z); d[3] = f2tf(av[i].w);
        uint32_t* e = &sB[lr * SAS + lk + i * 4];
        e[0] = f2tf(wv[i].x); e[1] = f2tf(wv[i].y);
        e[2] = f2tf(wv[i].z); e[3] = f2tf(wv[i].w);
    }
    __syncthreads();

    int p = 0;
    for (int k0 = 0; k0 < DIM; k0 += 32) {
        bool hasNext = (k0 + 32) < DIM;
        if (hasNext) {
            #pragma unroll
            for (int i = 0; i < 4; i++) {
                av[i] = *(const float4*)(Ap + k0 + 32 + i * 4);
                wv[i] = *(const float4*)(Wp + k0 + 32 + i * 4);
            }
        }

        const uint32_t* cA = sA + p * GSTG;
        const uint32_t* cB = sB + p * GSTG;
        #pragma unroll
        for (int ks = 0; ks < 4; ks++) {
            uint32_t af[4][4], bf[4][2];
            #pragma unroll
            for (int mt = 0; mt < 4; mt++) {
                int r = wm + mt * 16 + g, c = ks * 8 + q;
                af[mt][0] = cA[r * SAS + c];
                af[mt][1] = cA[(r + 8) * SAS + c];
                af[mt][2] = cA[r * SAS + c + 4];
                af[mt][3] = cA[(r + 8) * SAS + c + 4];
            }
            #pragma unroll
            for (int nt = 0; nt < 4; nt++) {
                int r = wn + nt * 8 + g, c = ks * 8 + q;
                bf[nt][0] = cB[r * SAS + c];
                bf[nt][1] = cB[r * SAS + c + 4];
            }
            #pragma unroll
            for (int mt = 0; mt < 4; mt++)
                #pragma unroll
                for (int nt = 0; nt < 4; nt++)
                    mma_tf32(acc[mt][nt], af[mt], bf[nt][0], bf[nt][1]);
        }

        if (hasNext) {
            uint32_t* nA = sA + (p ^ 1) * GSTG;
            uint32_t* nB = sB + (p ^ 1) * GSTG;
            #pragma unroll
            for (int i = 0; i < 4; i++) {
                uint32_t* d = &nA[lr * SAS + lk + i * 4];
                d[0] = f2tf(av[i].x); d[1] = f2tf(av[i].y);
                d[2] = f2tf(av[i].z); d[3] = f2tf(av[i].w);
                uint32_t* e = &nB[lr * SAS + lk + i * 4];
                e[0] = f2tf(wv[i].x); e[1] = f2tf(wv[i].y);
                e[2] = f2tf(wv[i].z); e[3] = f2tf(wv[i].w);
            }
        }
        __syncthreads();
        p ^= 1;
    }

    #pragma unroll
    for (int mt = 0; mt < 4; mt++) {
        #pragma unroll
        for (int nt = 0; nt < 4; nt++) {
            int row = m0 + wm + mt * 16 + g;
            int col = n0 + wn + nt * 8 + 2 * q;
            float b0 = bias ? bias[col] : 0.f;
            float b1 = bias ? bias[col + 1] : 0.f;
            float2 o0, o1;
            o0.x = acc[mt][nt][0] + b0; o0.y = acc[mt][nt][1] + b1;
            o1.x = acc[mt][nt][2] + b0; o1.y = acc[mt][nt][3] + b1;
            *(float2*)&C[(size_t)row * DIM + col] = o0;
            *(float2*)&C[(size_t)(row + 8) * DIM + col] = o1;
        }
    }
}

// ---------------- tensor-core flash attention with alibi (pipelined) ----------
// Block: 128 q-rows of one (b,h). 256 threads = 8 warps, warp owns 16 rows.
// KV tile = 64, double-buffered. Alibi init loads hoisted before mma loop.
#define KST 68   // sK / sPQ row stride
#define VST 72   // sV row stride
#define KSTG (64 * KST)
#define VSTG (64 * VST)

__global__ __launch_bounds__(256) void attn_tc(const float* __restrict__ alibi)
{
    extern __shared__ uint32_t dsm[];
    uint32_t* sK  = dsm;                         // 2 stages [64][KST]
    uint32_t* sV  = dsm + 2 * KSTG;              // 2 stages [64][VST]
    uint32_t* sPQ = dsm + 2 * KSTG + 2 * VSTG;   // [128][KST] (Q, then P per warp)

    int tid = threadIdx.x;
    int lane = tid & 31, w = tid >> 5;
    int g = lane >> 2, q = lane & 3;
    int bi = blockIdx.x, h = blockIdx.z, i0 = blockIdx.y * 128;

    // stage Q (scaled, tf32)
    {
        int r = tid >> 1;
        int cb = (tid & 1) * 32;
        const float* qp = g_q + ((size_t)(bi * SEQN + i0 + r)) * DIM + h * DH + cb;
        #pragma unroll
        for (int i = 0; i < 8; i++) {
            float4 t = *(const float4*)(qp + i * 4);
            uint32_t* d = &sPQ[r * KST + cb + i * 4];
            d[0] = f2tf(t.x * ATT_SCALE); d[1] = f2tf(t.y * ATT_SCALE);
            d[2] = f2tf(t.z * ATT_SCALE); d[3] = f2tf(t.w * ATT_SCALE);
        }
    }
    __syncthreads();

    uint32_t qf[8][4];
    #pragma unroll
    for (int ks = 0; ks < 8; ks++) {
        int r = w * 16 + g, c = ks * 8 + q;
        qf[ks][0] = sPQ[r * KST + c];
        qf[ks][1] = sPQ[(r + 8) * KST + c];
        qf[ks][2] = sPQ[r * KST + c + 4];
        qf[ks][3] = sPQ[(r + 8) * KST + c + 4];
    }
    __syncthreads();   // Q fragments consumed; sPQ now reusable for P

    float o[8][4];
    #pragma unroll
    for (int nt = 0; nt < 8; nt++)
        #pragma unroll
        for (int i = 0; i < 4; i++) o[nt][i] = 0.f;
    float m0r = -3.0e38f, m1r = -3.0e38f, l0 = 0.f, l1 = 0.f;

    const size_t alr0 = ((size_t)h * SEQN + (i0 + w * 16 + g)) * (size_t)SEQM + 2 * q;
    const size_t alr1 = alr0 + 8 * (size_t)SEQM;

    int kr = tid >> 2, kc = tid & 3;
    const float* kbase = g_k + ((size_t)(bi * SEQM + kr)) * DIM + h * DH;
    const float* vbase = g_v + ((size_t)(bi * SEQM + kr)) * DIM + h * DH;

    float4 kv4[4], vv4[4];
    // preload tile 0 into stage 0
    #pragma unroll
    for (int i = 0; i < 4; i++) {
        kv4[i] = *(const float4*)(kbase + kc * 4 + i * 16);
        vv4[i] = *(const float4*)(vbase + kc * 4 + i * 16);
    }
    #pragma unroll
    for (int i = 0; i < 4; i++) {
        int c = kc * 4 + i * 16;
        uint32_t* dk = &sK[kr * KST + c];
        dk[0] = f2tf(kv4[i].x); dk[1] = f2tf(kv4[i].y);
        dk[2] = f2tf(kv4[i].z); dk[3] = f2tf(kv4[i].w);
        uint32_t* dv = &sV[kr * VST + c];
        dv[0] = f2tf(vv4[i].x); dv[1] = f2tf(vv4[i].y);
        dv[2] = f2tf(vv4[i].z); dv[3] = f2tf(vv4[i].w);
    }
    __syncthreads();

    int p = 0;
    for (int j0 = 0; j0 < SEQM; j0 += 64) {
        bool hasNext = (j0 + 64) < SEQM;
        if (hasNext) {
            #pragma unroll
            for (int i = 0; i < 4; i++) {
                kv4[i] = *(const float4*)(kbase + (size_t)(j0 + 64) * DIM + kc * 4 + i * 16);
                vv4[i] = *(const float4*)(vbase + (size_t)(j0 + 64) * DIM + kc * 4 + i * 16);
            }
        }

        const uint32_t* cK = sK + p * KSTG;
        const uint32_t* cV = sV + p * VSTG;

        // init S accumulators from alibi first (hoisted LDGs), then mma
        float s[8][4];
        #pragma unroll
        for (int nt = 0; nt < 8; nt++) {
            float2 a0 = *(const float2*)(alibi + alr0 + j0 + nt * 8);
            float2 a1 = *(const float2*)(alibi + alr1 + j0 + nt * 8);
            s[nt][0] = a0.x; s[nt][1] = a0.y; s[nt][2] = a1.x; s[nt][3] = a1.y;
        }
        #pragma unroll
        for (int nt = 0; nt < 8; nt++) {
            #pragma unroll
            for (int ks = 0; ks < 8; ks++) {
                uint32_t b0 = cK[(nt * 8 + g) * KST + ks * 8 + q];
                uint32_t b1 = cK[(nt * 8 + g) * KST + ks * 8 + q + 4];
                mma_tf32(s[nt], qf[ks], b0, b1);
            }
        }

        // row max (2 rows per thread: g, g+8)
        float tm0 = -3.0e38f, tm1 = -3.0e38f;
        #pragma unroll
        for (int nt = 0; nt < 8; nt++) {
            tm0 = fmaxf(tm0, fmaxf(s[nt][0], s[nt][1]));
            tm1 = fmaxf(tm1, fmaxf(s[nt][2], s[nt][3]));
        }
        tm0 = fmaxf(tm0, __shfl_xor_sync(0xffffffffu, tm0, 1));
        tm0 = fmaxf(tm0, __shfl_xor_sync(0xffffffffu, tm0, 2));
        tm1 = fmaxf(tm1, __shfl_xor_sync(0xffffffffu, tm1, 1));
        tm1 = fmaxf(tm1, __shfl_xor_sync(0xffffffffu, tm1, 2));

        float mn0 = fmaxf(m0r, tm0), mn1 = fmaxf(m1r, tm1);
        float c0 = __expf(m0r - mn0), c1 = __expf(m1r - mn1);
        l0 *= c0; l1 *= c1;
        #pragma unroll
        for (int nt = 0; nt < 8; nt++) {
            o[nt][0] *= c0; o[nt][1] *= c0;
            o[nt][2] *= c1; o[nt][3] *= c1;
        }
        m0r = mn0; m1r = mn1;

        float ps0 = 0.f, ps1 = 0.f;
        int prow = w * 16 + g;
        #pragma unroll
        for (int nt = 0; nt < 8; nt++) {
            float p0 = __expf(s[nt][0] - mn0);
            float p1 = __expf(s[nt][1] - mn0);
            float p2 = __expf(s[nt][2] - mn1);
            float p3 = __expf(s[nt][3] - mn1);
            ps0 += p0 + p1; ps1 += p2 + p3;
            int col = nt * 8 + 2 * q;
            sPQ[prow * KST + col]     = f2tf(p0);
            sPQ[prow * KST + col + 1] = f2tf(p1);
            sPQ[(prow + 8) * KST + col]     = f2tf(p2);
            sPQ[(prow + 8) * KST + col + 1] = f2tf(p3);
        }
        ps0 += __shfl_xor_sync(0xffffffffu, ps0, 1);
        ps0 += __shfl_xor_sync(0xffffffffu, ps0, 2);
        ps1 += __shfl_xor_sync(0xffffffffu, ps1, 1);
        ps1 += __shfl_xor_sync(0xffffffffu, ps1, 2);
        l0 += ps0; l1 += ps1;

        __syncwarp();

        // O += P V
        #pragma unroll
        for (int ks = 0; ks < 8; ks++) {
            uint32_t af[4];
            af[0] = sPQ[prow * KST + ks * 8 + q];
            af[1] = sPQ[(prow + 8) * KST + ks * 8 + q];
            af[2] = sPQ[prow * KST + ks * 8 + q + 4];
            af[3] = sPQ[(prow + 8) * KST + ks * 8 + q + 4];
            #pragma unroll
            for (int nt = 0; nt < 8; nt++) {
                uint32_t b0 = cV[(ks * 8 + q) * VST + nt * 8 + g];
                uint32_t b1 = cV[(ks * 8 + q + 4) * VST + nt * 8 + g];
                mma_tf32(o[nt], af, b0, b1);
            }
        }

        if (hasNext) {
            uint32_t* nK = sK + (p ^ 1) * KSTG;
            uint32_t* nV = sV + (p ^ 1) * VSTG;
            #pragma unroll
            for (int i = 0; i < 4; i++) {
                int c = kc * 4 + i * 16;
                uint32_t* dk = &nK[kr * KST + c];
                dk[0] = f2tf(kv4[i].x); dk[1] = f2tf(kv4[i].y);
                dk[2] = f2tf(kv4[i].z); dk[3] = f2tf(kv4[i].w);
                uint32_t* dv = &nV[kr * VST + c];
                dv[0] = f2tf(vv4[i].x); dv[1] = f2tf(vv4[i].y);
                dv[2] = f2tf(vv4[i].z); dv[3] = f2tf(vv4[i].w);
            }
        }
        __syncthreads();
        p ^= 1;
    }

    float inv0 = 1.f / l0, inv1 = 1.f / l1;
    size_t orow = (size_t)(bi * SEQN + i0 + w * 16 + g) * DIM + h * DH;
    #pragma unroll
    for (int nt = 0; nt < 8; nt++) {
        int col = nt * 8 + 2 * q;
        float2 t0, t1;
        t0.x = o[nt][0] * inv0; t0.y = o[nt][1] * inv0;
        t1.x = o[nt][2] * inv1; t1.y = o[nt][3] * inv1;
        *(float2*)&g_ao[orow + col] = t0;
        *(float2*)&g_ao[orow + 8 * DIM + col] = t1;
    }
}

// ---------------- launch ----------------
extern "C" void kernel_launch(void* const* d_in, const int* in_sizes, int n_in,
                              void* d_out, int out_size)
{
    const float* x     = (const float*)d_in[0];
    const float* ctx   = (const float*)d_in[1];
    const float* alibi = (const float*)d_in[2];
    const float* Wq    = (const float*)d_in[3];
    const float* Wk    = (const float*)d_in[4];
    const float* Wv    = (const float*)d_in[5];
    const float* Wo    = (const float*)d_in[6];
    const float* bo    = (const float*)d_in[7];
    const float* ln_w  = (const float*)d_in[8];
    const float* ln_b  = (const float*)d_in[9];
    float* out = (float*)d_out;

    float *p_xn, *p_cn, *p_q, *p_k, *p_v, *p_ao;
    cudaGetSymbolAddress((void**)&p_xn, g_xn);
    cudaGetSymbolAddress((void**)&p_cn, g_cn);
    cudaGetSymbolAddress((void**)&p_q,  g_q);
    cudaGetSymbolAddress((void**)&p_k,  g_k);
    cudaGetSymbolAddress((void**)&p_v,  g_v);
    cudaGetSymbolAddress((void**)&p_ao, g_ao);

    const int gemm_smem = 4 * GSTG * 4;   // 2 stages x (sA+sB)
    const int attn_smem = (2 * KSTG + 2 * VSTG + 128 * KST) * 4;
    cudaFuncSetAttribute(gemm_tf32, cudaFuncAttributeMaxDynamicSharedMemorySize, gemm_smem);
    cudaFuncSetAttribute(attn_tc, cudaFuncAttributeMaxDynamicSharedMemorySize, attn_smem);

    // LayerNorm x and context
    ln_kernel<<<BATCH * SEQN + BATCH * SEQM, 256>>>(x, ctx, ln_w, ln_b, p_xn, p_cn);

    // Projections: y = xn @ W^T
    dim3 ggrid(DIM / 128, (BATCH * SEQN) / 128);
    gemm_tf32<<<ggrid, 256, gemm_smem>>>(p_xn, Wq, p_q, nullptr);
    gemm_tf32<<<ggrid, 256, gemm_smem>>>(p_cn, Wk, p_k, nullptr);
    gemm_tf32<<<ggrid, 256, gemm_smem>>>(p_cn, Wv, p_v, nullptr);

    // Flash attention with alibi; batch fastest so b=0/b=1 share alibi via L2
    dim3 agrid(BATCH, SEQN / 128, HEADS);
    attn_tc<<<agrid, 256, attn_smem>>>(alibi);

    // Output projection + bias -> d_out
    gemm_tf32<<<ggrid, 256, gemm_smem>>>(p_ao, Wo, out, bo);
}

// round 13
// speedup vs baseline: 1.1433x; 1.1433x over previous
#include <cuda_runtime.h>
#include <math.h>
#include <stdint.h>

#define BATCH 2
#define SEQN 2048
#define SEQM 2048
#define DIM 1024
#define HEADS 16
#define DH 64
#define ATT_SCALE 0.125f
#define LN_EPS 1e-5f

// ---------------- scratch (static device memory; no allocation) ----------------
__device__ float g_xn[BATCH * SEQN * DIM];
__device__ float g_cn[BATCH * SEQM * DIM];
__device__ float g_q [BATCH * SEQN * DIM];
__device__ float g_k [BATCH * SEQM * DIM];
__device__ float g_v [BATCH * SEQM * DIM];
__device__ float g_ao[BATCH * SEQN * DIM];

// ---------------- helpers ----------------
__device__ __forceinline__ uint32_t f2tf(float f) {
    uint32_t r;
    asm("cvt.rna.tf32.f32 %0, %1;" : "=r"(r) : "f"(f));
    return r;
}

__device__ __forceinline__ void mma_tf32(float* c, const uint32_t* a, uint32_t b0, uint32_t b1) {
    asm volatile(
        "mma.sync.aligned.m16n8k8.row.col.f32.tf32.tf32.f32 "
        "{%0,%1,%2,%3}, {%4,%5,%6,%7}, {%8,%9}, {%0,%1,%2,%3};\n"
        : "+f"(c[0]), "+f"(c[1]), "+f"(c[2]), "+f"(c[3])
        : "r"(a[0]), "r"(a[1]), "r"(a[2]), "r"(a[3]), "r"(b0), "r"(b1));
}

// ---------------- LayerNorm: one block per row ----------------
__global__ __launch_bounds__(256) void ln_kernel(
    const float* __restrict__ x, const float* __restrict__ ctx,
    const float* __restrict__ w, const float* __restrict__ b,
    float* __restrict__ xn, float* __restrict__ cn)
{
    int row = blockIdx.x;
    const float* in;
    float* out;
    if (row < BATCH * SEQN) {
        in = x + (size_t)row * DIM;
        out = xn + (size_t)row * DIM;
    } else {
        int r = row - BATCH * SEQN;
        in = ctx + (size_t)r * DIM;
        out = cn + (size_t)r * DIM;
    }
    int tid = threadIdx.x;
    float4 v4 = ((const float4*)in)[tid];
    float s  = v4.x + v4.y + v4.z + v4.w;
    float s2 = v4.x*v4.x + v4.y*v4.y + v4.z*v4.z + v4.w*v4.w;

    #pragma unroll
    for (int off = 16; off > 0; off >>= 1) {
        s  += __shfl_xor_sync(0xffffffffu, s,  off);
        s2 += __shfl_xor_sync(0xffffffffu, s2, off);
    }
    __shared__ float rs[8], rs2[8];
    int wid = tid >> 5, lid = tid & 31;
    if (lid == 0) { rs[wid] = s; rs2[wid] = s2; }
    __syncthreads();
    if (wid == 0) {
        s  = (lid < 8) ? rs[lid]  : 0.f;
        s2 = (lid < 8) ? rs2[lid] : 0.f;
        #pragma unroll
        for (int off = 4; off > 0; off >>= 1) {
            s  += __shfl_xor_sync(0xffffffffu, s,  off);
            s2 += __shfl_xor_sync(0xffffffffu, s2, off);
        }
        if (lid == 0) { rs[0] = s; rs2[0] = s2; }
    }
    __syncthreads();
    float mu  = rs[0] * (1.0f / DIM);
    float var = rs2[0] * (1.0f / DIM) - mu * mu;
    float inv = rsqrtf(var + LN_EPS);

    float4 w4 = ((const float4*)w)[tid];
    float4 b4 = ((const float4*)b)[tid];
    float4 o4;
    o4.x = (v4.x - mu) * inv * w4.x + b4.x;
    o4.y = (v4.y - mu) * inv * w4.y + b4.y;
    o4.z = (v4.z - mu) * inv * w4.z + b4.z;
    o4.w = (v4.w - mu) * inv * w4.w + b4.w;
    ((float4*)out)[tid] = o4;
}

// ---------------- tf32 GEMM body: C[M,N] = A[M,K] @ W[N,K]^T (+bias) --------
// 128x128 tile, BK=32, 256 threads (8 warps, 2x4), warp tile 64x32.
// Single-buffer smem, LDG prefetch into regs, LDS.64 fragment loads via
// consistent k-permutation (mma k-slots 0/1 <- physical cols 2q/2q+1 on BOTH
// operands, so every dot product sums the same 8 k-terms).
#define SAS 40   // stride mod 32 == 8 -> conflict-free uint2 fragment loads

__device__ __forceinline__ void gemm_body(
    const float* __restrict__ A, const float* __restrict__ W,
    float* __restrict__ C, const float* __restrict__ bias,
    uint32_t* sA, uint32_t* sB, int m0, int n0)
{
    int tid = threadIdx.x;
    int lane = tid & 31, w = tid >> 5;
    int g = lane >> 2, q = lane & 3;
    int wm = (w >> 2) * 64, wn = (w & 3) * 32;

    int lr = tid >> 1;          // 0..127
    int lk = (tid & 1) * 16;    // 0 or 16

    const float* Ap = A + (size_t)(m0 + lr) * DIM + lk;
    const float* Wp = W + (size_t)(n0 + lr) * DIM + lk;

    float acc[4][4][4];
    #pragma unroll
    for (int mt = 0; mt < 4; mt++)
        #pragma unroll
        for (int nt = 0; nt < 4; nt++)
            #pragma unroll
            for (int i = 0; i < 4; i++) acc[mt][nt][i] = 0.f;

    for (int k0 = 0; k0 < DIM; k0 += 32) {
        float4 av[4], wv[4];
        #pragma unroll
        for (int i = 0; i < 4; i++) {
            av[i] = *(const float4*)(Ap + k0 + i * 4);
            wv[i] = *(const float4*)(Wp + k0 + i * 4);
        }
        __syncthreads();
        #pragma unroll
        for (int i = 0; i < 4; i++) {
            *(uint4*)&sA[lr * SAS + lk + i * 4] =
                make_uint4(f2tf(av[i].x), f2tf(av[i].y), f2tf(av[i].z), f2tf(av[i].w));
            *(uint4*)&sB[lr * SAS + lk + i * 4] =
                make_uint4(f2tf(wv[i].x), f2tf(wv[i].y), f2tf(wv[i].z), f2tf(wv[i].w));
        }
        __syncthreads();

        #pragma unroll
        for (int ks = 0; ks < 4; ks++) {
            int c = ks * 8 + 2 * q;
            uint32_t af[4][4], bf[4][2];
            #pragma unroll
            for (int mt = 0; mt < 4; mt++) {
                int r = wm + mt * 16 + g;
                uint2 t0 = *(const uint2*)&sA[r * SAS + c];
                uint2 t1 = *(const uint2*)&sA[(r + 8) * SAS + c];
                af[mt][0] = t0.x; af[mt][2] = t0.y;
                af[mt][1] = t1.x; af[mt][3] = t1.y;
            }
            #pragma unroll
            for (int nt = 0; nt < 4; nt++) {
                int rn = wn + nt * 8 + g;
                uint2 tb = *(const uint2*)&sB[rn * SAS + c];
                bf[nt][0] = tb.x; bf[nt][1] = tb.y;
            }
            #pragma unroll
            for (int mt = 0; mt < 4; mt++)
                #pragma unroll
                for (int nt = 0; nt < 4; nt++)
                    mma_tf32(acc[mt][nt], af[mt], bf[nt][0], bf[nt][1]);
        }
    }

    #pragma unroll
    for (int mt = 0; mt < 4; mt++) {
        #pragma unroll
        for (int nt = 0; nt < 4; nt++) {
            int row = m0 + wm + mt * 16 + g;
            int col = n0 + wn + nt * 8 + 2 * q;
            float b0 = bias ? bias[col] : 0.f;
            float b1 = bias ? bias[col + 1] : 0.f;
            float2 o0, o1;
            o0.x = acc[mt][nt][0] + b0; o0.y = acc[mt][nt][1] + b1;
            o1.x = acc[mt][nt][2] + b0; o1.y = acc[mt][nt][3] + b1;
            *(float2*)&C[(size_t)row * DIM + col] = o0;
            *(float2*)&C[(size_t)(row + 8) * DIM + col] = o1;
        }
    }
}

// Fused Q/K/V projections: blockIdx.z selects {Wq->q, Wk->k, Wv->v}.
__global__ __launch_bounds__(256) void gemm_qkv(
    const float* __restrict__ Wq, const float* __restrict__ Wk,
    const float* __restrict__ Wv)
{
    __shared__ uint32_t sA[128 * SAS];
    __shared__ uint32_t sB[128 * SAS];
    int z = blockIdx.z;
    const float* A = (z == 0) ? g_xn : g_cn;
    const float* W = (z == 0) ? Wq : (z == 1) ? Wk : Wv;
    float* C = (z == 0) ? g_q : (z == 1) ? g_k : g_v;
    gemm_body(A, W, C, nullptr, sA, sB, blockIdx.y * 128, blockIdx.x * 128);
}

// Output projection with bias.
__global__ __launch_bounds__(256) void gemm_out(
    const float* __restrict__ W, float* __restrict__ C,
    const float* __restrict__ bias)
{
    __shared__ uint32_t sA[128 * SAS];
    __shared__ uint32_t sB[128 * SAS];
    gemm_body(g_ao, W, C, bias, sA, sB, blockIdx.y * 128, blockIdx.x * 128);
}

// ---------------- tensor-core flash attention with alibi --------------------
// Block: 128 q-rows of one (b,h). 256 threads = 8 warps, warp owns 16 rows.
// KV tile = 64, single buffer (occupancy). LDS.64 fragment loads (k-perm).
#define KST 72   // stride mod 32 == 8: conflict-free for row-by-g indexed loads
#define VST 68   // stride mod 32 == 4: conflict-free for row-by-2q indexed loads

__global__ __launch_bounds__(256) void attn_tc(const float* __restrict__ alibi)
{
    extern __shared__ uint32_t dsm[];
    uint32_t* sK  = dsm;                         // [64][KST]
    uint32_t* sV  = dsm + 64 * KST;              // [64][VST]
    uint32_t* sPQ = dsm + 64 * KST + 64 * VST;   // [128][KST] (Q, then P)

    int tid = threadIdx.x;
    int lane = tid & 31, w = tid >> 5;
    int g = lane >> 2, q = lane & 3;
    int bi = blockIdx.x, h = blockIdx.z, i0 = blockIdx.y * 128;

    // stage Q (scaled, tf32)
    {
        int r = tid >> 1;
        int cb = (tid & 1) * 32;
        const float* qp = g_q + ((size_t)(bi * SEQN + i0 + r)) * DIM + h * DH + cb;
        #pragma unroll
        for (int i = 0; i < 8; i++) {
            float4 t = *(const float4*)(qp + i * 4);
            *(uint4*)&sPQ[r * KST + cb + i * 4] =
                make_uint4(f2tf(t.x * ATT_SCALE), f2tf(t.y * ATT_SCALE),
                           f2tf(t.z * ATT_SCALE), f2tf(t.w * ATT_SCALE));
        }
    }
    __syncthreads();

    uint32_t qf[8][4];
    #pragma unroll
    for (int ks = 0; ks < 8; ks++) {
        int r = w * 16 + g, c = ks * 8 + 2 * q;
        uint2 t0 = *(const uint2*)&sPQ[r * KST + c];
        uint2 t1 = *(const uint2*)&sPQ[(r + 8) * KST + c];
        qf[ks][0] = t0.x; qf[ks][2] = t0.y;
        qf[ks][1] = t1.x; qf[ks][3] = t1.y;
    }
    __syncthreads();   // Q fragments consumed; sPQ now reusable for P

    float o[8][4];
    #pragma unroll
    for (int nt = 0; nt < 8; nt++)
        #pragma unroll
        for (int i = 0; i < 4; i++) o[nt][i] = 0.f;
    float m0r = -3.0e38f, m1r = -3.0e38f, l0 = 0.f, l1 = 0.f;

    const size_t alr0 = ((size_t)h * SEQN + (i0 + w * 16 + g)) * (size_t)SEQM + 2 * q;
    const size_t alr1 = alr0 + 8 * (size_t)SEQM;

    int kr = tid >> 2, kc = tid & 3;
    const float* kbase = g_k + ((size_t)(bi * SEQM + kr)) * DIM + h * DH;
    const float* vbase = g_v + ((size_t)(bi * SEQM + kr)) * DIM + h * DH;

    for (int j0 = 0; j0 < SEQM; j0 += 64) {
        // prefetch K/V tile into regs
        float4 kv4[4], vv4[4];
        #pragma unroll
        for (int i = 0; i < 4; i++) {
            kv4[i] = *(const float4*)(kbase + (size_t)j0 * DIM + kc * 4 + i * 16);
            vv4[i] = *(const float4*)(vbase + (size_t)j0 * DIM + kc * 4 + i * 16);
        }
        __syncthreads();
        #pragma unroll
        for (int i = 0; i < 4; i++) {
            int c = kc * 4 + i * 16;
            *(uint4*)&sK[kr * KST + c] =
                make_uint4(f2tf(kv4[i].x), f2tf(kv4[i].y), f2tf(kv4[i].z), f2tf(kv4[i].w));
            *(uint4*)&sV[kr * VST + c] =
                make_uint4(f2tf(vv4[i].x), f2tf(vv4[i].y), f2tf(vv4[i].z), f2tf(vv4[i].w));
        }
        __syncthreads();

        // S = alibi + Q K^T (alibi LDGs hoisted ahead of mma chain)
        float s[8][4];
        #pragma unroll
        for (int nt = 0; nt < 8; nt++) {
            float2 a0 = *(const float2*)(alibi + alr0 + j0 + nt * 8);
            float2 a1 = *(const float2*)(alibi + alr1 + j0 + nt * 8);
            s[nt][0] = a0.x; s[nt][1] = a0.y; s[nt][2] = a1.x; s[nt][3] = a1.y;
        }
        #pragma unroll
        for (int nt = 0; nt < 8; nt++) {
            #pragma unroll
            for (int ks = 0; ks < 8; ks++) {
                uint2 tb = *(const uint2*)&sK[(nt * 8 + g) * KST + ks * 8 + 2 * q];
                mma_tf32(s[nt], qf[ks], tb.x, tb.y);
            }
        }

        // row max (2 rows per thread: g, g+8)
        float tm0 = -3.0e38f, tm1 = -3.0e38f;
        #pragma unroll
        for (int nt = 0; nt < 8; nt++) {
            tm0 = fmaxf(tm0, fmaxf(s[nt][0], s[nt][1]));
            tm1 = fmaxf(tm1, fmaxf(s[nt][2], s[nt][3]));
        }
        tm0 = fmaxf(tm0, __shfl_xor_sync(0xffffffffu, tm0, 1));
        tm0 = fmaxf(tm0, __shfl_xor_sync(0xffffffffu, tm0, 2));
        tm1 = fmaxf(tm1, __shfl_xor_sync(0xffffffffu, tm1, 1));
        tm1 = fmaxf(tm1, __shfl_xor_sync(0xffffffffu, tm1, 2));

        float mn0 = fmaxf(m0r, tm0), mn1 = fmaxf(m1r, tm1);
        float c0 = __expf(m0r - mn0), c1 = __expf(m1r - mn1);
        l0 *= c0; l1 *= c1;
        #pragma unroll
        for (int nt = 0; nt < 8; nt++) {
            o[nt][0] *= c0; o[nt][1] *= c0;
            o[nt][2] *= c1; o[nt][3] *= c1;
        }
        m0r = mn0; m1r = mn1;

        float ps0 = 0.f, ps1 = 0.f;
        int prow = w * 16 + g;
        #pragma unroll
        for (int nt = 0; nt < 8; nt++) {
            float p0 = __expf(s[nt][0] - mn0);
            float p1 = __expf(s[nt][1] - mn0);
            float p2 = __expf(s[nt][2] - mn1);
            float p3 = __expf(s[nt][3] - mn1);
            ps0 += p0 + p1; ps1 += p2 + p3;
            int col = nt * 8 + 2 * q;
            *(uint2*)&sPQ[prow * KST + col]       = make_uint2(f2tf(p0), f2tf(p1));
            *(uint2*)&sPQ[(prow + 8) * KST + col] = make_uint2(f2tf(p2), f2tf(p3));
        }
        ps0 += __shfl_xor_sync(0xffffffffu, ps0, 1);
        ps0 += __shfl_xor_sync(0xffffffffu, ps0, 2);
        ps1 += __shfl_xor_sync(0xffffffffu, ps1, 1);
        ps1 += __shfl_xor_sync(0xffffffffu, ps1, 2);
        l0 += ps0; l1 += ps1;

        // P rows for this warp are written and read only by this warp
        __syncwarp();

        // O += P V  (P slot0/1 <- cols 2q/2q+1; V rows 2q/2q+1: consistent k-order)
        #pragma unroll
        for (int ks = 0; ks < 8; ks++) {
            int c = ks * 8 + 2 * q;
            uint32_t af[4];
            uint2 t0 = *(const uint2*)&sPQ[prow * KST + c];
            uint2 t1 = *(const uint2*)&sPQ[(prow + 8) * KST + c];
            af[0] = t0.x; af[2] = t0.y;
            af[1] = t1.x; af[3] = t1.y;
            #pragma unroll
            for (int nt = 0; nt < 8; nt++) {
                uint32_t b0 = sV[(c) * VST + nt * 8 + g];
                uint32_t b1 = sV[(c + 1) * VST + nt * 8 + g];
                mma_tf32(o[nt], af, b0, b1);
            }
        }
    }

    float inv0 = 1.f / l0, inv1 = 1.f / l1;
    size_t orow = (size_t)(bi * SEQN + i0 + w * 16 + g) * DIM + h * DH;
    #pragma unroll
    for (int nt = 0; nt < 8; nt++) {
        int col = nt * 8 + 2 * q;
        float2 t0, t1;
        t0.x = o[nt][0] * inv0; t0.y = o[nt][1] * inv0;
        t1.x = o[nt][2] * inv1; t1.y = o[nt][3] * inv1;
        *(float2*)&g_ao[orow + col] = t0;
        *(float2*)&g_ao[orow + 8 * DIM + col] = t1;
    }
}

// ---------------- launch ----------------
extern "C" void kernel_launch(void* const* d_in, const int* in_sizes, int n_in,
                              void* d_out, int out_size)
{
    const float* x     = (const float*)d_in[0];
    const float* ctx   = (const float*)d_in[1];
    const float* alibi = (const float*)d_in[2];
    const float* Wq    = (const float*)d_in[3];
    const float* Wk    = (const float*)d_in[4];
    const float* Wv    = (const float*)d_in[5];
    const float* Wo    = (const float*)d_in[6];
    const float* bo    = (const float*)d_in[7];
    const float* ln_w  = (const float*)d_in[8];
    const float* ln_b  = (const float*)d_in[9];
    float* out = (float*)d_out;

    float *p_xn, *p_cn;
    cudaGetSymbolAddress((void**)&p_xn, g_xn);
    cudaGetSymbolAddress((void**)&p_cn, g_cn);

    const int attn_smem = (64 * KST + 64 * VST + 128 * KST) * 4;
    cudaFuncSetAttribute(attn_tc, cudaFuncAttributeMaxDynamicSharedMemorySize, attn_smem);

    // LayerNorm x and context
    ln_kernel<<<BATCH * SEQN + BATCH * SEQM, 256>>>(x, ctx, ln_w, ln_b, p_xn, p_cn);

    // Fused Q/K/V projections (one launch, 768 CTAs)
    dim3 qkvgrid(DIM / 128, (BATCH * SEQN) / 128, 3);
    gemm_qkv<<<qkvgrid, 256>>>(Wq, Wk, Wv);

    // Flash attention with alibi; batch fastest so b=0/b=1 share alibi via L2
    dim3 agrid(BATCH, SEQN / 128, HEADS);
    attn_tc<<<agrid, 256, attn_smem>>>(alibi);

    // Output projection + bias -> d_out
    dim3 ogrid(DIM / 128, (BATCH * SEQN) / 128);
    gemm_out<<<ogrid, 256>>>(Wo, out, bo);
}